// round 1
// baseline (speedup 1.0000x reference)
#include <cuda_runtime.h>

// Problem constants
#define BN 65536
#define KK 16
#define DD 64
#define HH 128
#define ZZ 16

// Tiling
#define TM 64          // samples per block tile
#define PAD 68         // TM + 4 padding (keeps float4 alignment, spreads banks)

// -------- scratch (static device globals; no allocation allowed) --------
__device__ int   g_counts[KK];
__device__ int   g_cursor[KK];
__device__ int   g_offsets[KK + 1];
__device__ int   g_sorted[BN];
__device__ float g_act[(size_t)BN * HH];   // backbone output, stored at sorted position

// ------------------------- bucketing kernels ----------------------------
__global__ void k_init() {
    if (threadIdx.x < KK) g_counts[threadIdx.x] = 0;
}

__global__ void k_hist(const int* __restrict__ y) {
    int i = blockIdx.x * blockDim.x + threadIdx.x;
    if (i < BN) atomicAdd(&g_counts[y[i]], 1);
}

__global__ void k_scan() {
    // single thread, K=16 — trivial
    int off = 0;
    for (int k = 0; k < KK; k++) {
        g_offsets[k] = off;
        g_cursor[k]  = off;
        off += g_counts[k];
    }
    g_offsets[KK] = off;
}

__global__ void k_scatter(const int* __restrict__ y) {
    int i = blockIdx.x * blockDim.x + threadIdx.x;
    if (i < BN) {
        int pos = atomicAdd(&g_cursor[y[i]], 1);
        g_sorted[pos] = i;
    }
}

// ------------------------- backbone kernel ------------------------------
// Each block: TM=64 samples (in sorted order), 256 threads.
// Thread (j = tid&127, half = tid>>7) computes feature j for 32 samples.
// Activations live transposed in smem: sa[feature][sample] so the inner
// loop reads broadcast float4 over samples.
__global__ __launch_bounds__(256) void k_backbone(
    const float* __restrict__ z,
    const float* __restrict__ bw0, const float* __restrict__ bb0,
    const float* __restrict__ bw1, const float* __restrict__ bb1,
    const float* __restrict__ bw2, const float* __restrict__ bb2,
    const float* __restrict__ bw3, const float* __restrict__ bb3)
{
    __shared__ __align__(16) float sz[ZZ][PAD];
    __shared__ __align__(16) float sa[HH][PAD];

    const int base = blockIdx.x * TM;
    const int tid  = threadIdx.x;

    // gather z for this tile, transposed: sz[i][t]
    for (int e = tid; e < TM * ZZ; e += 256) {
        int t = e >> 4, i = e & (ZZ - 1);
        int s = g_sorted[base + t];
        sz[i][t] = z[(size_t)s * ZZ + i];
    }
    __syncthreads();

    const int j  = tid & (HH - 1);
    const int t0 = (tid >> 7) * 32;
    float acc[32];

    // ---- layer 0: Z -> H, ReLU ----
    {
        float bias = bb0[j];
#pragma unroll
        for (int t = 0; t < 32; t++) acc[t] = bias;
#pragma unroll
        for (int i = 0; i < ZZ; i++) {
            float w = bw0[i * HH + j];
#pragma unroll
            for (int q = 0; q < 8; q++) {
                float4 a4 = *reinterpret_cast<const float4*>(&sz[i][t0 + q * 4]);
                acc[q*4+0] = fmaf(a4.x, w, acc[q*4+0]);
                acc[q*4+1] = fmaf(a4.y, w, acc[q*4+1]);
                acc[q*4+2] = fmaf(a4.z, w, acc[q*4+2]);
                acc[q*4+3] = fmaf(a4.w, w, acc[q*4+3]);
            }
        }
#pragma unroll
        for (int q = 0; q < 8; q++) {
            float4 v;
            v.x = fmaxf(acc[q*4+0], 0.f);
            v.y = fmaxf(acc[q*4+1], 0.f);
            v.z = fmaxf(acc[q*4+2], 0.f);
            v.w = fmaxf(acc[q*4+3], 0.f);
            *reinterpret_cast<float4*>(&sa[j][t0 + q * 4]) = v;
        }
        __syncthreads();
    }

    // ---- layers 1,2: H -> H, ReLU, stay in smem ----
#pragma unroll 1
    for (int L = 0; L < 2; L++) {
        const float* W  = (L == 0) ? bw1 : bw2;
        const float* Bv = (L == 0) ? bb1 : bb2;
        float bias = Bv[j];
#pragma unroll
        for (int t = 0; t < 32; t++) acc[t] = bias;
#pragma unroll 4
        for (int i = 0; i < HH; i++) {
            float w = W[i * HH + j];
#pragma unroll
            for (int q = 0; q < 8; q++) {
                float4 a4 = *reinterpret_cast<const float4*>(&sa[i][t0 + q * 4]);
                acc[q*4+0] = fmaf(a4.x, w, acc[q*4+0]);
                acc[q*4+1] = fmaf(a4.y, w, acc[q*4+1]);
                acc[q*4+2] = fmaf(a4.z, w, acc[q*4+2]);
                acc[q*4+3] = fmaf(a4.w, w, acc[q*4+3]);
            }
        }
        __syncthreads();   // everyone done reading sa before overwrite
#pragma unroll
        for (int q = 0; q < 8; q++) {
            float4 v;
            v.x = fmaxf(acc[q*4+0], 0.f);
            v.y = fmaxf(acc[q*4+1], 0.f);
            v.z = fmaxf(acc[q*4+2], 0.f);
            v.w = fmaxf(acc[q*4+3], 0.f);
            *reinterpret_cast<float4*>(&sa[j][t0 + q * 4]) = v;
        }
        __syncthreads();
    }

    // ---- layer 3: H -> H, ReLU, write straight to g_act (sorted order) ----
    {
        float bias = bb3[j];
#pragma unroll
        for (int t = 0; t < 32; t++) acc[t] = bias;
#pragma unroll 4
        for (int i = 0; i < HH; i++) {
            float w = bw3[i * HH + j];
#pragma unroll
            for (int q = 0; q < 8; q++) {
                float4 a4 = *reinterpret_cast<const float4*>(&sa[i][t0 + q * 4]);
                acc[q*4+0] = fmaf(a4.x, w, acc[q*4+0]);
                acc[q*4+1] = fmaf(a4.y, w, acc[q*4+1]);
                acc[q*4+2] = fmaf(a4.z, w, acc[q*4+2]);
                acc[q*4+3] = fmaf(a4.w, w, acc[q*4+3]);
            }
        }
#pragma unroll
        for (int t = 0; t < 32; t++) {
            g_act[(size_t)(base + t0 + t) * HH + j] = fmaxf(acc[t], 0.f);
        }
    }
}

// --------------------------- head kernel --------------------------------
// grid = (tiles, K). Block handles TM rows of expert k's bucket.
// All 4 head layers fused; activations stay in (transposed) smem.
__global__ __launch_bounds__(256) void k_heads(
    const float* __restrict__ hw0, const float* __restrict__ hb0,
    const float* __restrict__ hw1, const float* __restrict__ hb1,
    const float* __restrict__ hw2, const float* __restrict__ hb2,
    const float* __restrict__ hw3, const float* __restrict__ hb3,
    float* __restrict__ out)
{
    __shared__ __align__(16) float sa[HH][PAD];

    const int k      = blockIdx.y;
    const int cstart = g_offsets[k];
    const int cend   = g_offsets[k + 1];
    const int base   = cstart + blockIdx.x * TM;
    if (base >= cend) return;     // uniform early exit

    const int tid = threadIdx.x;

    // load activations for this tile (zero-pad beyond bucket end), transposed
    for (int e = tid; e < TM * HH; e += 256) {
        int t = e >> 7, i = e & (HH - 1);
        float v = 0.f;
        if (base + t < cend) v = g_act[(size_t)(base + t) * HH + i];
        sa[i][t] = v;
    }
    __syncthreads();

    const int j  = tid & (HH - 1);
    const int t0 = (tid >> 7) * 32;
    float acc[32];

    // ---- head layers 0..2: H -> H, ReLU ----
#pragma unroll 1
    for (int L = 0; L < 3; L++) {
        const float* W  = (L == 0) ? (hw0 + (size_t)k * HH * HH)
                        : (L == 1) ? (hw1 + (size_t)k * HH * HH)
                                   : (hw2 + (size_t)k * HH * HH);
        const float* Bv = (L == 0) ? (hb0 + k * HH)
                        : (L == 1) ? (hb1 + k * HH)
                                   : (hb2 + k * HH);
        float bias = Bv[j];
#pragma unroll
        for (int t = 0; t < 32; t++) acc[t] = bias;
#pragma unroll 4
        for (int i = 0; i < HH; i++) {
            float w = W[i * HH + j];
#pragma unroll
            for (int q = 0; q < 8; q++) {
                float4 a4 = *reinterpret_cast<const float4*>(&sa[i][t0 + q * 4]);
                acc[q*4+0] = fmaf(a4.x, w, acc[q*4+0]);
                acc[q*4+1] = fmaf(a4.y, w, acc[q*4+1]);
                acc[q*4+2] = fmaf(a4.z, w, acc[q*4+2]);
                acc[q*4+3] = fmaf(a4.w, w, acc[q*4+3]);
            }
        }
        __syncthreads();
#pragma unroll
        for (int q = 0; q < 8; q++) {
            float4 v;
            v.x = fmaxf(acc[q*4+0], 0.f);
            v.y = fmaxf(acc[q*4+1], 0.f);
            v.z = fmaxf(acc[q*4+2], 0.f);
            v.w = fmaxf(acc[q*4+3], 0.f);
            *reinterpret_cast<float4*>(&sa[j][t0 + q * 4]) = v;
        }
        __syncthreads();
    }

    // ---- head layer 3: H -> D (=64), no ReLU, scatter to output ----
    {
        const int j2 = tid & (DD - 1);      // feature 0..63
        const int q0 = (tid >> 6) * 16;     // 4 row-groups of 16
        float bias = hb3[k * DD + j2];
        float acc2[16];
#pragma unroll
        for (int t = 0; t < 16; t++) acc2[t] = bias;
        const float* W3 = hw3 + (size_t)k * HH * DD;
#pragma unroll 4
        for (int i = 0; i < HH; i++) {
            float w = W3[i * DD + j2];
#pragma unroll
            for (int q = 0; q < 4; q++) {
                float4 a4 = *reinterpret_cast<const float4*>(&sa[i][q0 + q * 4]);
                acc2[q*4+0] = fmaf(a4.x, w, acc2[q*4+0]);
                acc2[q*4+1] = fmaf(a4.y, w, acc2[q*4+1]);
                acc2[q*4+2] = fmaf(a4.z, w, acc2[q*4+2]);
                acc2[q*4+3] = fmaf(a4.w, w, acc2[q*4+3]);
            }
        }
#pragma unroll
        for (int t = 0; t < 16; t++) {
            int p = base + q0 + t;
            if (p < cend) {
                int s = g_sorted[p];
                out[(size_t)s * DD + j2] = acc2[t];
            }
        }
    }
}

// ----------------------------- launcher ----------------------------------
extern "C" void kernel_launch(void* const* d_in, const int* in_sizes, int n_in,
                              void* d_out, int out_size)
{
    const float* z   = (const float*)d_in[0];
    const int*   y   = (const int*)  d_in[1];
    const float* bw0 = (const float*)d_in[2];
    const float* bb0 = (const float*)d_in[3];
    const float* bw1 = (const float*)d_in[4];
    const float* bb1 = (const float*)d_in[5];
    const float* bw2 = (const float*)d_in[6];
    const float* bb2 = (const float*)d_in[7];
    const float* bw3 = (const float*)d_in[8];
    const float* bb3 = (const float*)d_in[9];
    const float* hw0 = (const float*)d_in[10];
    const float* hb0 = (const float*)d_in[11];
    const float* hw1 = (const float*)d_in[12];
    const float* hb1 = (const float*)d_in[13];
    const float* hw2 = (const float*)d_in[14];
    const float* hb2 = (const float*)d_in[15];
    const float* hw3 = (const float*)d_in[16];
    const float* hb3 = (const float*)d_in[17];
    float* out = (float*)d_out;

    k_init<<<1, 32>>>();
    k_hist<<<BN / 256, 256>>>(y);
    k_scan<<<1, 1>>>();
    k_scatter<<<BN / 256, 256>>>(y);
    k_backbone<<<BN / TM, 256>>>(z, bw0, bb0, bw1, bb1, bw2, bb2, bw3, bb3);
    dim3 hgrid(BN / TM, KK);   // per-expert tiles, uniform early exit past bucket end
    k_heads<<<hgrid, 256>>>(hw0, hb0, hw1, hb1, hw2, hb2, hw3, hb3, out);
}

// round 2
// speedup vs baseline: 1.0003x; 1.0003x over previous
#include <cuda_runtime.h>

// Problem constants
#define BN 65536
#define KK 16
#define DD 64
#define HH 128
#define ZZ 16

// Tiling
#define TM 64          // samples per block tile
#define PAD 68         // TM + 4 padding (keeps float4 alignment, spreads banks)

// -------- scratch (static device globals; no allocation allowed) --------
__device__ int   g_counts[KK];
__device__ int   g_cursor[KK];
__device__ int   g_offsets[KK + 1];
__device__ int   g_sorted[BN];
__device__ float g_act[(size_t)BN * HH];   // backbone output, stored at sorted position

// ------------------------- bucketing kernels ----------------------------
__global__ void k_init() {
    if (threadIdx.x < KK) g_counts[threadIdx.x] = 0;
}

__global__ void k_hist(const int* __restrict__ y) {
    int i = blockIdx.x * blockDim.x + threadIdx.x;
    if (i < BN) atomicAdd(&g_counts[y[i]], 1);
}

__global__ void k_scan() {
    // single thread, K=16 — trivial
    int off = 0;
    for (int k = 0; k < KK; k++) {
        g_offsets[k] = off;
        g_cursor[k]  = off;
        off += g_counts[k];
    }
    g_offsets[KK] = off;
}

__global__ void k_scatter(const int* __restrict__ y) {
    int i = blockIdx.x * blockDim.x + threadIdx.x;
    if (i < BN) {
        int pos = atomicAdd(&g_cursor[y[i]], 1);
        g_sorted[pos] = i;
    }
}

// ------------------------- backbone kernel ------------------------------
// Each block: TM=64 samples (in sorted order), 256 threads.
// Thread (j = tid&127, half = tid>>7) computes feature j for 32 samples.
// Activations live transposed in smem: sa[feature][sample] so the inner
// loop reads broadcast float4 over samples.
__global__ __launch_bounds__(256) void k_backbone(
    const float* __restrict__ z,
    const float* __restrict__ bw0, const float* __restrict__ bb0,
    const float* __restrict__ bw1, const float* __restrict__ bb1,
    const float* __restrict__ bw2, const float* __restrict__ bb2,
    const float* __restrict__ bw3, const float* __restrict__ bb3)
{
    __shared__ __align__(16) float sz[ZZ][PAD];
    __shared__ __align__(16) float sa[HH][PAD];

    const int base = blockIdx.x * TM;
    const int tid  = threadIdx.x;

    // gather z for this tile, transposed: sz[i][t]
    for (int e = tid; e < TM * ZZ; e += 256) {
        int t = e >> 4, i = e & (ZZ - 1);
        int s = g_sorted[base + t];
        sz[i][t] = z[(size_t)s * ZZ + i];
    }
    __syncthreads();

    const int j  = tid & (HH - 1);
    const int t0 = (tid >> 7) * 32;
    float acc[32];

    // ---- layer 0: Z -> H, ReLU ----
    {
        float bias = bb0[j];
#pragma unroll
        for (int t = 0; t < 32; t++) acc[t] = bias;
#pragma unroll
        for (int i = 0; i < ZZ; i++) {
            float w = bw0[i * HH + j];
#pragma unroll
            for (int q = 0; q < 8; q++) {
                float4 a4 = *reinterpret_cast<const float4*>(&sz[i][t0 + q * 4]);
                acc[q*4+0] = fmaf(a4.x, w, acc[q*4+0]);
                acc[q*4+1] = fmaf(a4.y, w, acc[q*4+1]);
                acc[q*4+2] = fmaf(a4.z, w, acc[q*4+2]);
                acc[q*4+3] = fmaf(a4.w, w, acc[q*4+3]);
            }
        }
#pragma unroll
        for (int q = 0; q < 8; q++) {
            float4 v;
            v.x = fmaxf(acc[q*4+0], 0.f);
            v.y = fmaxf(acc[q*4+1], 0.f);
            v.z = fmaxf(acc[q*4+2], 0.f);
            v.w = fmaxf(acc[q*4+3], 0.f);
            *reinterpret_cast<float4*>(&sa[j][t0 + q * 4]) = v;
        }
        __syncthreads();
    }

    // ---- layers 1,2: H -> H, ReLU, stay in smem ----
#pragma unroll 1
    for (int L = 0; L < 2; L++) {
        const float* W  = (L == 0) ? bw1 : bw2;
        const float* Bv = (L == 0) ? bb1 : bb2;
        float bias = Bv[j];
#pragma unroll
        for (int t = 0; t < 32; t++) acc[t] = bias;
#pragma unroll 4
        for (int i = 0; i < HH; i++) {
            float w = W[i * HH + j];
#pragma unroll
            for (int q = 0; q < 8; q++) {
                float4 a4 = *reinterpret_cast<const float4*>(&sa[i][t0 + q * 4]);
                acc[q*4+0] = fmaf(a4.x, w, acc[q*4+0]);
                acc[q*4+1] = fmaf(a4.y, w, acc[q*4+1]);
                acc[q*4+2] = fmaf(a4.z, w, acc[q*4+2]);
                acc[q*4+3] = fmaf(a4.w, w, acc[q*4+3]);
            }
        }
        __syncthreads();   // everyone done reading sa before overwrite
#pragma unroll
        for (int q = 0; q < 8; q++) {
            float4 v;
            v.x = fmaxf(acc[q*4+0], 0.f);
            v.y = fmaxf(acc[q*4+1], 0.f);
            v.z = fmaxf(acc[q*4+2], 0.f);
            v.w = fmaxf(acc[q*4+3], 0.f);
            *reinterpret_cast<float4*>(&sa[j][t0 + q * 4]) = v;
        }
        __syncthreads();
    }

    // ---- layer 3: H -> H, ReLU, write straight to g_act (sorted order) ----
    {
        float bias = bb3[j];
#pragma unroll
        for (int t = 0; t < 32; t++) acc[t] = bias;
#pragma unroll 4
        for (int i = 0; i < HH; i++) {
            float w = bw3[i * HH + j];
#pragma unroll
            for (int q = 0; q < 8; q++) {
                float4 a4 = *reinterpret_cast<const float4*>(&sa[i][t0 + q * 4]);
                acc[q*4+0] = fmaf(a4.x, w, acc[q*4+0]);
                acc[q*4+1] = fmaf(a4.y, w, acc[q*4+1]);
                acc[q*4+2] = fmaf(a4.z, w, acc[q*4+2]);
                acc[q*4+3] = fmaf(a4.w, w, acc[q*4+3]);
            }
        }
#pragma unroll
        for (int t = 0; t < 32; t++) {
            g_act[(size_t)(base + t0 + t) * HH + j] = fmaxf(acc[t], 0.f);
        }
    }
}

// --------------------------- head kernel --------------------------------
// grid = (tiles, K). Block handles TM rows of expert k's bucket.
// All 4 head layers fused; activations stay in (transposed) smem.
__global__ __launch_bounds__(256) void k_heads(
    const float* __restrict__ hw0, const float* __restrict__ hb0,
    const float* __restrict__ hw1, const float* __restrict__ hb1,
    const float* __restrict__ hw2, const float* __restrict__ hb2,
    const float* __restrict__ hw3, const float* __restrict__ hb3,
    float* __restrict__ out)
{
    __shared__ __align__(16) float sa[HH][PAD];

    const int k      = blockIdx.y;
    const int cstart = g_offsets[k];
    const int cend   = g_offsets[k + 1];
    const int base   = cstart + blockIdx.x * TM;
    if (base >= cend) return;     // uniform early exit

    const int tid = threadIdx.x;

    // load activations for this tile (zero-pad beyond bucket end), transposed
    for (int e = tid; e < TM * HH; e += 256) {
        int t = e >> 7, i = e & (HH - 1);
        float v = 0.f;
        if (base + t < cend) v = g_act[(size_t)(base + t) * HH + i];
        sa[i][t] = v;
    }
    __syncthreads();

    const int j  = tid & (HH - 1);
    const int t0 = (tid >> 7) * 32;
    float acc[32];

    // ---- head layers 0..2: H -> H, ReLU ----
#pragma unroll 1
    for (int L = 0; L < 3; L++) {
        const float* W  = (L == 0) ? (hw0 + (size_t)k * HH * HH)
                        : (L == 1) ? (hw1 + (size_t)k * HH * HH)
                                   : (hw2 + (size_t)k * HH * HH);
        const float* Bv = (L == 0) ? (hb0 + k * HH)
                        : (L == 1) ? (hb1 + k * HH)
                                   : (hb2 + k * HH);
        float bias = Bv[j];
#pragma unroll
        for (int t = 0; t < 32; t++) acc[t] = bias;
#pragma unroll 4
        for (int i = 0; i < HH; i++) {
            float w = W[i * HH + j];
#pragma unroll
            for (int q = 0; q < 8; q++) {
                float4 a4 = *reinterpret_cast<const float4*>(&sa[i][t0 + q * 4]);
                acc[q*4+0] = fmaf(a4.x, w, acc[q*4+0]);
                acc[q*4+1] = fmaf(a4.y, w, acc[q*4+1]);
                acc[q*4+2] = fmaf(a4.z, w, acc[q*4+2]);
                acc[q*4+3] = fmaf(a4.w, w, acc[q*4+3]);
            }
        }
        __syncthreads();
#pragma unroll
        for (int q = 0; q < 8; q++) {
            float4 v;
            v.x = fmaxf(acc[q*4+0], 0.f);
            v.y = fmaxf(acc[q*4+1], 0.f);
            v.z = fmaxf(acc[q*4+2], 0.f);
            v.w = fmaxf(acc[q*4+3], 0.f);
            *reinterpret_cast<float4*>(&sa[j][t0 + q * 4]) = v;
        }
        __syncthreads();
    }

    // ---- head layer 3: H -> D (=64), no ReLU, scatter to output ----
    {
        const int j2 = tid & (DD - 1);      // feature 0..63
        const int q0 = (tid >> 6) * 16;     // 4 row-groups of 16
        float bias = hb3[k * DD + j2];
        float acc2[16];
#pragma unroll
        for (int t = 0; t < 16; t++) acc2[t] = bias;
        const float* W3 = hw3 + (size_t)k * HH * DD;
#pragma unroll 4
        for (int i = 0; i < HH; i++) {
            float w = W3[i * DD + j2];
#pragma unroll
            for (int q = 0; q < 4; q++) {
                float4 a4 = *reinterpret_cast<const float4*>(&sa[i][q0 + q * 4]);
                acc2[q*4+0] = fmaf(a4.x, w, acc2[q*4+0]);
                acc2[q*4+1] = fmaf(a4.y, w, acc2[q*4+1]);
                acc2[q*4+2] = fmaf(a4.z, w, acc2[q*4+2]);
                acc2[q*4+3] = fmaf(a4.w, w, acc2[q*4+3]);
            }
        }
#pragma unroll
        for (int t = 0; t < 16; t++) {
            int p = base + q0 + t;
            if (p < cend) {
                int s = g_sorted[p];
                out[(size_t)s * DD + j2] = acc2[t];
            }
        }
    }
}

// ----------------------------- launcher ----------------------------------
extern "C" void kernel_launch(void* const* d_in, const int* in_sizes, int n_in,
                              void* d_out, int out_size)
{
    const float* z   = (const float*)d_in[0];
    const int*   y   = (const int*)  d_in[1];
    const float* bw0 = (const float*)d_in[2];
    const float* bb0 = (const float*)d_in[3];
    const float* bw1 = (const float*)d_in[4];
    const float* bb1 = (const float*)d_in[5];
    const float* bw2 = (const float*)d_in[6];
    const float* bb2 = (const float*)d_in[7];
    const float* bw3 = (const float*)d_in[8];
    const float* bb3 = (const float*)d_in[9];
    const float* hw0 = (const float*)d_in[10];
    const float* hb0 = (const float*)d_in[11];
    const float* hw1 = (const float*)d_in[12];
    const float* hb1 = (const float*)d_in[13];
    const float* hw2 = (const float*)d_in[14];
    const float* hb2 = (const float*)d_in[15];
    const float* hw3 = (const float*)d_in[16];
    const float* hb3 = (const float*)d_in[17];
    float* out = (float*)d_out;

    k_init<<<1, 32>>>();
    k_hist<<<BN / 256, 256>>>(y);
    k_scan<<<1, 1>>>();
    k_scatter<<<BN / 256, 256>>>(y);
    k_backbone<<<BN / TM, 256>>>(z, bw0, bb0, bw1, bb1, bw2, bb2, bw3, bb3);
    dim3 hgrid(BN / TM, KK);   // per-expert tiles, uniform early exit past bucket end
    k_heads<<<hgrid, 256>>>(hw0, hb0, hw1, hb1, hw2, hb2, hw3, hb3, out);
}

// round 3
// speedup vs baseline: 1.4241x; 1.4236x over previous
#include <cuda_runtime.h>
#include <cstdint>

// Problem constants
#define BN 65536
#define KK 16
#define DD 64
#define HH 128
#define ZZ 16

#define TM 64           // samples per block tile
#define RS 272          // smem row stride in floats (16-bank shift per row)
#define HT 96           // max tiles per expert bucket (96*64 = 6144 >> max bucket)

// -------- scratch (static device globals; no allocation allowed) --------
__device__ int   g_counts[KK];
__device__ int   g_cursor[KK];
__device__ int   g_offsets[KK + 1];
__device__ int   g_sorted[BN];
__device__ float g_act[(size_t)BN * HH];      // backbone output at sorted position
__device__ float g_wsplit[1937408];           // tf32 hi/lo split weights, permuted

// split-weight offsets (floats)
#define OFF_BW0 0
#define OFF_BW1 4096
#define OFF_BW2 36864
#define OFF_BW3 69632
#define OFF_HW0 102400
#define OFF_HW1 626688
#define OFF_HW2 1150976
#define OFF_HW3 1675264

// ------------------------- tf32 helpers ----------------------------
__device__ __forceinline__ float to_tf32(float x) {
    uint32_t u;
    asm("cvt.rna.tf32.f32 %0, %1;" : "=r"(u) : "f"(x));
    return __uint_as_float(u);
}
__device__ __forceinline__ void split_tf32(float x, float& hi, float& lo) {
    hi = to_tf32(x);
    lo = to_tf32(x - hi);
}
__device__ __forceinline__ void mma8(float c[4], uint32_t a0, uint32_t a1,
                                     uint32_t a2, uint32_t a3,
                                     uint32_t b0, uint32_t b1) {
    asm volatile(
        "mma.sync.aligned.m16n8k8.row.col.f32.tf32.tf32.f32 "
        "{%0,%1,%2,%3}, {%4,%5,%6,%7}, {%8,%9}, {%0,%1,%2,%3};"
        : "+f"(c[0]), "+f"(c[1]), "+f"(c[2]), "+f"(c[3])
        : "r"(a0), "r"(a1), "r"(a2), "r"(a3), "r"(b0), "r"(b1));
}

// slot permutation within a k-group of 8: pairs (0,4),(1,5),(2,6),(3,7)
__device__ __forceinline__ int kslot(int k) { return 2 * (k & 3) + ((k >> 2) & 1); }

// store one fp32 value split into the permuted smem activation layout
__device__ __forceinline__ void store_split_smem(float* sa, int r, int c, float v) {
    float hi, lo;
    split_tf32(v, hi, lo);
    int kg = c >> 3;
    int s  = kslot(c & 7);
    *reinterpret_cast<float2*>(&sa[r * RS + kg * 16 + s * 2]) = make_float2(hi, lo);
}

// ------------------------- bucketing kernels ----------------------------
__global__ void k_init() {
    if (threadIdx.x < KK) g_counts[threadIdx.x] = 0;
}
__global__ void k_hist(const int* __restrict__ y) {
    int i = blockIdx.x * blockDim.x + threadIdx.x;
    if (i < BN) atomicAdd(&g_counts[y[i]], 1);
}
__global__ void k_scan() {
    int off = 0;
    for (int k = 0; k < KK; k++) {
        g_offsets[k] = off;
        g_cursor[k]  = off;
        off += g_counts[k];
    }
    g_offsets[KK] = off;
}
__global__ void k_scatter(const int* __restrict__ y) {
    int i = blockIdx.x * blockDim.x + threadIdx.x;
    if (i < BN) {
        int pos = atomicAdd(&g_cursor[y[i]], 1);
        g_sorted[pos] = i;
    }
}

// ----------------------- weight split kernel ---------------------------
// W[in][out] row-major -> dst[out][in/8][slot][2] (hi,lo)
__device__ __forceinline__ void wsplit_one(const float* __restrict__ W, float* dst,
                                           int In, int Out, int idx) {
    int in  = idx / Out;
    int out = idx % Out;
    float hi, lo;
    split_tf32(W[idx], hi, lo);
    int o = out * In * 2 + (in >> 3) * 16 + kslot(in & 7) * 2;
    dst[o]     = hi;
    dst[o + 1] = lo;
}

__global__ void k_wsplit(
    const float* __restrict__ bw0, const float* __restrict__ bw1,
    const float* __restrict__ bw2, const float* __restrict__ bw3,
    const float* __restrict__ hw0, const float* __restrict__ hw1,
    const float* __restrict__ hw2, const float* __restrict__ hw3)
{
    int i = blockIdx.x * blockDim.x + threadIdx.x;
    if (i < 2048) {
        wsplit_one(bw0, g_wsplit + OFF_BW0, 16, 128, i);
    } else if (i < 18432) {
        wsplit_one(bw1, g_wsplit + OFF_BW1, 128, 128, i - 2048);
    } else if (i < 34816) {
        wsplit_one(bw2, g_wsplit + OFF_BW2, 128, 128, i - 18432);
    } else if (i < 51200) {
        wsplit_one(bw3, g_wsplit + OFF_BW3, 128, 128, i - 34816);
    } else if (i < 313344) {
        int j = i - 51200;  int e = j / 16384;
        wsplit_one(hw0 + (size_t)e * 16384, g_wsplit + OFF_HW0 + (size_t)e * 32768,
                   128, 128, j % 16384);
    } else if (i < 575488) {
        int j = i - 313344; int e = j / 16384;
        wsplit_one(hw1 + (size_t)e * 16384, g_wsplit + OFF_HW1 + (size_t)e * 32768,
                   128, 128, j % 16384);
    } else if (i < 837632) {
        int j = i - 575488; int e = j / 16384;
        wsplit_one(hw2 + (size_t)e * 16384, g_wsplit + OFF_HW2 + (size_t)e * 32768,
                   128, 128, j % 16384);
    } else if (i < 968704) {
        int j = i - 837632; int e = j / 8192;
        wsplit_one(hw3 + (size_t)e * 8192, g_wsplit + OFF_HW3 + (size_t)e * 16384,
                   128, 64, j % 8192);
    }
}

// ----------------------- warp-level 3xTF32 GEMM ------------------------
// Warp tile: 32 samples (m0..m0+31) x NT*8 outputs (n0..). C[2][4][4] frags.
template<int KSTEPS, int NT>
__device__ __forceinline__ void gemm_warp(
    const float* sa, const float* __restrict__ Wt, int In2,
    int m0, int n0, int g, int tig, float C[2][4][4])
{
    const float* a0p = &sa[(m0 +      g) * RS + 4 * tig];
    const float* a1p = &sa[(m0 +  8 + g) * RS + 4 * tig];
    const float* a2p = &sa[(m0 + 16 + g) * RS + 4 * tig];
    const float* a3p = &sa[(m0 + 24 + g) * RS + 4 * tig];
    const float* bp[NT];
#pragma unroll
    for (int nt = 0; nt < NT; nt++)
        bp[nt] = &Wt[(size_t)(n0 + nt * 8 + g) * In2 + 4 * tig];

#pragma unroll 2
    for (int kg = 0; kg < KSTEPS; kg++) {
        uint4 A0 = *reinterpret_cast<const uint4*>(a0p + kg * 16);
        uint4 A1 = *reinterpret_cast<const uint4*>(a1p + kg * 16);
        uint4 A2 = *reinterpret_cast<const uint4*>(a2p + kg * 16);
        uint4 A3 = *reinterpret_cast<const uint4*>(a3p + kg * 16);
#pragma unroll
        for (int nt = 0; nt < NT; nt++) {
            uint4 Bv = *reinterpret_cast<const uint4*>(bp[nt] + kg * 16);
            // m-frag 0 (rows m0..m0+15): hi*hi, hi*lo, lo*hi
            mma8(C[0][nt], A0.x, A1.x, A0.z, A1.z, Bv.x, Bv.z);
            mma8(C[0][nt], A0.x, A1.x, A0.z, A1.z, Bv.y, Bv.w);
            mma8(C[0][nt], A0.y, A1.y, A0.w, A1.w, Bv.x, Bv.z);
            // m-frag 1 (rows m0+16..m0+31)
            mma8(C[1][nt], A2.x, A3.x, A2.z, A3.z, Bv.x, Bv.z);
            mma8(C[1][nt], A2.x, A3.x, A2.z, A3.z, Bv.y, Bv.w);
            mma8(C[1][nt], A2.y, A3.y, A2.w, A3.w, Bv.x, Bv.z);
        }
    }
}

template<int NT>
__device__ __forceinline__ void init_bias(float C[2][4][4], const float* __restrict__ bias,
                                          int n0, int tig) {
#pragma unroll
    for (int nt = 0; nt < NT; nt++) {
        float b0 = bias[n0 + nt * 8 + 2 * tig];
        float b1 = bias[n0 + nt * 8 + 2 * tig + 1];
#pragma unroll
        for (int mf = 0; mf < 2; mf++) {
            C[mf][nt][0] = b0; C[mf][nt][1] = b1;
            C[mf][nt][2] = b0; C[mf][nt][3] = b1;
        }
    }
}

// epilogue: ReLU + split-store back to smem (NT n-tiles)
template<int NT>
__device__ __forceinline__ void epi_relu_split(float* sa, float C[2][4][4],
                                               int m0, int n0, int g, int tig) {
#pragma unroll
    for (int mf = 0; mf < 2; mf++) {
        int r0 = m0 + mf * 16 + g;
        int r1 = r0 + 8;
#pragma unroll
        for (int nt = 0; nt < NT; nt++) {
            int c = n0 + nt * 8 + 2 * tig;
            store_split_smem(sa, r0, c,     fmaxf(C[mf][nt][0], 0.f));
            store_split_smem(sa, r0, c + 1, fmaxf(C[mf][nt][1], 0.f));
            store_split_smem(sa, r1, c,     fmaxf(C[mf][nt][2], 0.f));
            store_split_smem(sa, r1, c + 1, fmaxf(C[mf][nt][3], 0.f));
        }
    }
}

// ------------------------- backbone kernel ------------------------------
__global__ __launch_bounds__(256) void k_backbone_mma(
    const float* __restrict__ z,
    const float* __restrict__ bb0, const float* __restrict__ bb1,
    const float* __restrict__ bb2, const float* __restrict__ bb3)
{
    extern __shared__ __align__(16) float sa[];
    const int base = blockIdx.x * TM;
    const int tid  = threadIdx.x;

    // stage z: gather + split + permute
    for (int e = tid; e < TM * ZZ; e += 256) {
        int t = e >> 4, i = e & (ZZ - 1);
        float v = z[(size_t)g_sorted[base + t] * ZZ + i];
        store_split_smem(sa, t, i, v);
    }
    __syncthreads();

    const int wid  = tid >> 5;
    const int lane = tid & 31;
    const int g    = lane >> 2;
    const int tig  = lane & 3;
    const int m0   = (wid & 1) * 32;
    const int n0   = (wid >> 1) * 32;

    float C[2][4][4];

    // layer 0: Z(16) -> H
    init_bias<4>(C, bb0, n0, tig);
    gemm_warp<2, 4>(sa, g_wsplit + OFF_BW0, ZZ * 2, m0, n0, g, tig, C);
    __syncthreads();
    epi_relu_split<4>(sa, C, m0, n0, g, tig);
    __syncthreads();

    // layer 1
    init_bias<4>(C, bb1, n0, tig);
    gemm_warp<16, 4>(sa, g_wsplit + OFF_BW1, HH * 2, m0, n0, g, tig, C);
    __syncthreads();
    epi_relu_split<4>(sa, C, m0, n0, g, tig);
    __syncthreads();

    // layer 2
    init_bias<4>(C, bb2, n0, tig);
    gemm_warp<16, 4>(sa, g_wsplit + OFF_BW2, HH * 2, m0, n0, g, tig, C);
    __syncthreads();
    epi_relu_split<4>(sa, C, m0, n0, g, tig);
    __syncthreads();

    // layer 3: ReLU, store PLAIN fp32 into sa rows [r][0..127], then coalesce out
    init_bias<4>(C, bb3, n0, tig);
    gemm_warp<16, 4>(sa, g_wsplit + OFF_BW3, HH * 2, m0, n0, g, tig, C);
    __syncthreads();
#pragma unroll
    for (int mf = 0; mf < 2; mf++) {
        int r0 = m0 + mf * 16 + g;
        int r1 = r0 + 8;
#pragma unroll
        for (int nt = 0; nt < 4; nt++) {
            int c = n0 + nt * 8 + 2 * tig;
            *reinterpret_cast<float2*>(&sa[r0 * RS + c]) =
                make_float2(fmaxf(C[mf][nt][0], 0.f), fmaxf(C[mf][nt][1], 0.f));
            *reinterpret_cast<float2*>(&sa[r1 * RS + c]) =
                make_float2(fmaxf(C[mf][nt][2], 0.f), fmaxf(C[mf][nt][3], 0.f));
        }
    }
    __syncthreads();
    // coalesced store to g_act (sorted order)
    for (int e = tid; e < TM * (HH / 4); e += 256) {
        int r = e >> 5, c4 = (e & 31) * 4;
        float4 v = *reinterpret_cast<const float4*>(&sa[r * RS + c4]);
        *reinterpret_cast<float4*>(&g_act[(size_t)(base + r) * HH + c4]) = v;
    }
}

// --------------------------- head kernel --------------------------------
__global__ __launch_bounds__(256) void k_heads_mma(
    const float* __restrict__ hb0, const float* __restrict__ hb1,
    const float* __restrict__ hb2, const float* __restrict__ hb3,
    float* __restrict__ out)
{
    extern __shared__ __align__(16) float sa[];
    const int k      = blockIdx.y;
    const int cstart = g_offsets[k];
    const int cend   = g_offsets[k + 1];
    const int base   = cstart + blockIdx.x * TM;
    if (base >= cend) return;

    const int tid = threadIdx.x;

    // load activations (zero-pad past bucket end), split + permute into smem
    for (int e = tid; e < TM * (HH / 4); e += 256) {
        int r = e >> 5, c4 = (e & 31) * 4;
        float4 v = make_float4(0.f, 0.f, 0.f, 0.f);
        if (base + r < cend)
            v = *reinterpret_cast<const float4*>(&g_act[(size_t)(base + r) * HH + c4]);
        store_split_smem(sa, r, c4 + 0, v.x);
        store_split_smem(sa, r, c4 + 1, v.y);
        store_split_smem(sa, r, c4 + 2, v.z);
        store_split_smem(sa, r, c4 + 3, v.w);
    }
    __syncthreads();

    const int wid  = tid >> 5;
    const int lane = tid & 31;
    const int g    = lane >> 2;
    const int tig  = lane & 3;
    const int m0   = (wid & 1) * 32;
    const int n0   = (wid >> 1) * 32;

    float C[2][4][4];

    const float* w0 = g_wsplit + OFF_HW0 + (size_t)k * (HH * HH * 2);
    const float* w1 = g_wsplit + OFF_HW1 + (size_t)k * (HH * HH * 2);
    const float* w2 = g_wsplit + OFF_HW2 + (size_t)k * (HH * HH * 2);
    const float* w3 = g_wsplit + OFF_HW3 + (size_t)k * (HH * DD * 2);

    init_bias<4>(C, hb0 + k * HH, n0, tig);
    gemm_warp<16, 4>(sa, w0, HH * 2, m0, n0, g, tig, C);
    __syncthreads();
    epi_relu_split<4>(sa, C, m0, n0, g, tig);
    __syncthreads();

    init_bias<4>(C, hb1 + k * HH, n0, tig);
    gemm_warp<16, 4>(sa, w1, HH * 2, m0, n0, g, tig, C);
    __syncthreads();
    epi_relu_split<4>(sa, C, m0, n0, g, tig);
    __syncthreads();

    init_bias<4>(C, hb2 + k * HH, n0, tig);
    gemm_warp<16, 4>(sa, w2, HH * 2, m0, n0, g, tig, C);
    __syncthreads();
    epi_relu_split<4>(sa, C, m0, n0, g, tig);
    __syncthreads();

    // layer 3: H -> D(64), no ReLU. Remap: 4 n-quarters of 16 (NT=2).
    {
        const int n3 = (wid >> 1) * 16;
        init_bias<2>(C, hb3 + k * DD, n3, tig);
        gemm_warp<16, 2>(sa, w3, HH * 2, m0, n3, g, tig, C);
#pragma unroll
        for (int mf = 0; mf < 2; mf++) {
            int r0 = m0 + mf * 16 + g;
            int r1 = r0 + 8;
#pragma unroll
            for (int nt = 0; nt < 2; nt++) {
                int c = n3 + nt * 8 + 2 * tig;
                int p0 = base + r0, p1 = base + r1;
                if (p0 < cend) {
                    int s = g_sorted[p0];
                    *reinterpret_cast<float2*>(&out[(size_t)s * DD + c]) =
                        make_float2(C[mf][nt][0], C[mf][nt][1]);
                }
                if (p1 < cend) {
                    int s = g_sorted[p1];
                    *reinterpret_cast<float2*>(&out[(size_t)s * DD + c]) =
                        make_float2(C[mf][nt][2], C[mf][nt][3]);
                }
            }
        }
    }
}

// ----------------------------- launcher ----------------------------------
#define SMEM_BYTES (TM * RS * 4)

extern "C" void kernel_launch(void* const* d_in, const int* in_sizes, int n_in,
                              void* d_out, int out_size)
{
    const float* z   = (const float*)d_in[0];
    const int*   y   = (const int*)  d_in[1];
    const float* bw0 = (const float*)d_in[2];
    const float* bb0 = (const float*)d_in[3];
    const float* bw1 = (const float*)d_in[4];
    const float* bb1 = (const float*)d_in[5];
    const float* bw2 = (const float*)d_in[6];
    const float* bb2 = (const float*)d_in[7];
    const float* bw3 = (const float*)d_in[8];
    const float* bb3 = (const float*)d_in[9];
    const float* hw0 = (const float*)d_in[10];
    const float* hb0 = (const float*)d_in[11];
    const float* hw1 = (const float*)d_in[12];
    const float* hb1 = (const float*)d_in[13];
    const float* hw2 = (const float*)d_in[14];
    const float* hb2 = (const float*)d_in[15];
    const float* hw3 = (const float*)d_in[16];
    const float* hb3 = (const float*)d_in[17];
    float* out = (float*)d_out;

    cudaFuncSetAttribute(k_backbone_mma, cudaFuncAttributeMaxDynamicSharedMemorySize, SMEM_BYTES);
    cudaFuncSetAttribute(k_heads_mma,    cudaFuncAttributeMaxDynamicSharedMemorySize, SMEM_BYTES);

    k_init<<<1, 32>>>();
    k_hist<<<BN / 256, 256>>>(y);
    k_scan<<<1, 1>>>();
    k_scatter<<<BN / 256, 256>>>(y);
    k_wsplit<<<(968704 + 255) / 256, 256>>>(bw0, bw1, bw2, bw3, hw0, hw1, hw2, hw3);
    k_backbone_mma<<<BN / TM, 256, SMEM_BYTES>>>(z, bb0, bb1, bb2, bb3);
    dim3 hgrid(HT, KK);
    k_heads_mma<<<hgrid, 256, SMEM_BYTES>>>(hb0, hb1, hb2, hb3, out);
}

// round 4
// speedup vs baseline: 3.0913x; 2.1707x over previous
#include <cuda_runtime.h>
#include <cuda_bf16.h>
#include <cstdint>

#define BN 65536
#define KK 16
#define DD 64
#define HH 128
#define ZZ 16
#define TM 64            // samples per block tile
#define NBLK 64          // hist/scatter blocks
#define TPB_H 1024
#define HT 80            // tiles per bucket covered (80*64=5120 >> E[bucket]+16sigma)
#define RSU 36           // smem row stride in uint4 (576B; ==64 mod 128B: conflict-free LDS.128)

// -------- device-global scratch (no allocation allowed) --------
__device__ int   g_counts[KK];
__device__ int   g_offsets[KK + 1];
__device__ int   g_bbase[NBLK][KK];
__device__ int   g_sorted[BN];
__device__ uint4 g_wsplit[242176];   // bf16 hi/lo split weights, fragment-permuted

// offsets in uint4 slots (slot = 4 k-positions for one output col)
#define OFF_BW0 0
#define OFF_BW1 512
#define OFF_BW2 4608
#define OFF_BW3 8704
#define OFF_HW0 12800
#define OFF_HW1 78336
#define OFF_HW2 143872
#define OFF_HW3 209408

// ------------------------- bf16 split helpers ----------------------------
__device__ __forceinline__ void bsplit(float x, float& hi, float& lo) {
    __nv_bfloat16 h = __float2bfloat16_rn(x);
    hi = __bfloat162float(h);
    lo = x - hi;                      // exact in fp32
}
__device__ __forceinline__ uint32_t bfpack(float a, float b) {
    uint16_t ua = __bfloat16_as_ushort(__float2bfloat16_rn(a));
    uint16_t ub = __bfloat16_as_ushort(__float2bfloat16_rn(b));
    return (uint32_t)ua | ((uint32_t)ub << 16);   // low half = lower k
}
__device__ __forceinline__ void mma16(float c[4], uint32_t a0, uint32_t a1,
                                      uint32_t a2, uint32_t a3,
                                      uint32_t b0, uint32_t b1) {
    asm volatile(
        "mma.sync.aligned.m16n8k16.row.col.f32.bf16.bf16.f32 "
        "{%0,%1,%2,%3}, {%4,%5,%6,%7}, {%8,%9}, {%0,%1,%2,%3};"
        : "+f"(c[0]), "+f"(c[1]), "+f"(c[2]), "+f"(c[3])
        : "r"(a0), "r"(a1), "r"(a2), "r"(a3), "r"(b0), "r"(b1));
}

// ------------------------- bucketing (aggregated) -------------------------
__global__ void k_init() { if (threadIdx.x < KK) g_counts[threadIdx.x] = 0; }

__global__ __launch_bounds__(TPB_H) void k_hist(const int* __restrict__ y) {
    __shared__ int cnt[KK];
    int tid = threadIdx.x;
    if (tid < KK) cnt[tid] = 0;
    __syncthreads();
    int base = blockIdx.x * (BN / NBLK);
    for (int i = tid; i < BN / NBLK; i += TPB_H)
        atomicAdd(&cnt[y[base + i]], 1);
    __syncthreads();
    if (tid < KK)
        g_bbase[blockIdx.x][tid] = atomicAdd(&g_counts[tid], cnt[tid]);
}

__global__ void k_scan() {
    int off = 0;
    for (int k = 0; k < KK; k++) { g_offsets[k] = off; off += g_counts[k]; }
    g_offsets[KK] = off;
}

__global__ __launch_bounds__(TPB_H) void k_scatter(const int* __restrict__ y) {
    __shared__ int cur[KK];
    int tid = threadIdx.x;
    if (tid < KK) cur[tid] = 0;
    __syncthreads();
    int base = blockIdx.x * (BN / NBLK);
    for (int i = tid; i < BN / NBLK; i += TPB_H) {
        int k = y[base + i];
        int r = atomicAdd(&cur[k], 1);
        g_sorted[g_offsets[k] + g_bbase[blockIdx.x][k] + r] = base + i;
    }
}

// ----------------------- weight split kernel -----------------------------
// W[in][out] row-major -> per out col: KG kgroups x 4 slots of uint4
// slot t covers k in {2t, 2t+1, 2t+8, 2t+9} within its kgroup:
//   .x=[hi k2t, hi k2t+1] .y=[hi k2t+8, hi k2t+9] .z/.w = lo same
__device__ __forceinline__ void wsplit_slot(const float* __restrict__ W, uint4* dst,
                                            int In, int Out, int s) {
    int out = s / (In / 4);
    int rem = s % (In / 4);
    int kg = rem >> 2, t = rem & 3;
    int k0 = kg * 16 + 2 * t;
    float w0 = W[(size_t)(k0    ) * Out + out];
    float w1 = W[(size_t)(k0 + 1) * Out + out];
    float w2 = W[(size_t)(k0 + 8) * Out + out];
    float w3 = W[(size_t)(k0 + 9) * Out + out];
    float h0,l0,h1,l1,h2,l2,h3,l3;
    bsplit(w0,h0,l0); bsplit(w1,h1,l1); bsplit(w2,h2,l2); bsplit(w3,h3,l3);
    uint4 v;
    v.x = bfpack(h0,h1); v.y = bfpack(h2,h3);
    v.z = bfpack(l0,l1); v.w = bfpack(l2,l3);
    dst[s] = v;
}

__global__ void k_wsplit(
    const float* __restrict__ bw0, const float* __restrict__ bw1,
    const float* __restrict__ bw2, const float* __restrict__ bw3,
    const float* __restrict__ hw0, const float* __restrict__ hw1,
    const float* __restrict__ hw2, const float* __restrict__ hw3)
{
    int i = blockIdx.x * blockDim.x + threadIdx.x;
    if (i < 512) {
        wsplit_slot(bw0, g_wsplit + OFF_BW0, 16, 128, i);
    } else if (i < 4608) {
        wsplit_slot(bw1, g_wsplit + OFF_BW1, 128, 128, i - 512);
    } else if (i < 8704) {
        wsplit_slot(bw2, g_wsplit + OFF_BW2, 128, 128, i - 4608);
    } else if (i < 12800) {
        wsplit_slot(bw3, g_wsplit + OFF_BW3, 128, 128, i - 8704);
    } else if (i < 78336) {
        int j = i - 12800; int e = j >> 12;
        wsplit_slot(hw0 + (size_t)e * 16384, g_wsplit + OFF_HW0 + (size_t)e * 4096,
                    128, 128, j & 4095);
    } else if (i < 143872) {
        int j = i - 78336; int e = j >> 12;
        wsplit_slot(hw1 + (size_t)e * 16384, g_wsplit + OFF_HW1 + (size_t)e * 4096,
                    128, 128, j & 4095);
    } else if (i < 209408) {
        int j = i - 143872; int e = j >> 12;
        wsplit_slot(hw2 + (size_t)e * 16384, g_wsplit + OFF_HW2 + (size_t)e * 4096,
                    128, 128, j & 4095);
    } else if (i < 242176) {
        int j = i - 209408; int e = j >> 11;
        wsplit_slot(hw3 + (size_t)e * 8192, g_wsplit + OFF_HW3 + (size_t)e * 2048,
                    128, 64, j & 2047);
    }
}

// ----------------------- warp-level 3xBF16 GEMM --------------------------
// Warp tile: 32 samples x NT*8 outputs. KG = In/16 kgroups.
template<int KG, int NT>
__device__ __forceinline__ void gemm_warp(
    const uint4* sa, const uint4* __restrict__ Wt,
    int m0, int n0, int g, int t, float C[2][4][4])
{
    const uint4* a0p = sa + (m0      + g) * RSU + t;
    const uint4* a1p = sa + (m0 + 8  + g) * RSU + t;
    const uint4* a2p = sa + (m0 + 16 + g) * RSU + t;
    const uint4* a3p = sa + (m0 + 24 + g) * RSU + t;
    const uint4* bp[NT];
#pragma unroll
    for (int nt = 0; nt < NT; nt++)
        bp[nt] = Wt + (size_t)(n0 + nt * 8 + g) * (KG * 4) + t;

#pragma unroll 2
    for (int kg = 0; kg < KG; kg++) {
        uint4 A0 = a0p[kg * 4];
        uint4 A1 = a1p[kg * 4];
        uint4 A2 = a2p[kg * 4];
        uint4 A3 = a3p[kg * 4];
#pragma unroll
        for (int nt = 0; nt < NT; nt++) {
            uint4 B = bp[nt][kg * 4];
            // m-frag 0: hi*hi, hi*lo(b), lo(a)*hi
            mma16(C[0][nt], A0.x, A1.x, A0.y, A1.y, B.x, B.y);
            mma16(C[0][nt], A0.x, A1.x, A0.y, A1.y, B.z, B.w);
            mma16(C[0][nt], A0.z, A1.z, A0.w, A1.w, B.x, B.y);
            // m-frag 1
            mma16(C[1][nt], A2.x, A3.x, A2.y, A3.y, B.x, B.y);
            mma16(C[1][nt], A2.x, A3.x, A2.y, A3.y, B.z, B.w);
            mma16(C[1][nt], A2.z, A3.z, A2.w, A3.w, B.x, B.y);
        }
    }
}

template<int NT>
__device__ __forceinline__ void init_bias(float C[2][4][4],
                                          const float* __restrict__ bias,
                                          int n0, int t) {
#pragma unroll
    for (int nt = 0; nt < NT; nt++) {
        float b0 = bias[n0 + nt * 8 + 2 * t];
        float b1 = bias[n0 + nt * 8 + 2 * t + 1];
#pragma unroll
        for (int mf = 0; mf < 2; mf++) {
            C[mf][nt][0] = b0; C[mf][nt][1] = b1;
            C[mf][nt][2] = b0; C[mf][nt][3] = b1;
        }
    }
}

// epilogue: ReLU + bf16 split-store back into smem activation layout
template<int NT>
__device__ __forceinline__ void epi_relu_split(uint4* sa, float C[2][4][4],
                                               int m0, int n0, int g, int t) {
#pragma unroll
    for (int mf = 0; mf < 2; mf++) {
#pragma unroll
        for (int half = 0; half < 2; half++) {
            int r = m0 + mf * 16 + half * 8 + g;
            uint32_t* rowp = reinterpret_cast<uint32_t*>(sa + r * RSU);
#pragma unroll
            for (int nt = 0; nt < NT; nt++) {
                float v0 = fmaxf(C[mf][nt][half * 2 + 0], 0.f);
                float v1 = fmaxf(C[mf][nt][half * 2 + 1], 0.f);
                float h0, l0, h1, l1;
                bsplit(v0, h0, l0); bsplit(v1, h1, l1);
                int kg  = (n0 >> 4) + (nt >> 1);
                int idx = kg * 16 + t * 4 + (nt & 1);
                rowp[idx]     = bfpack(h0, h1);
                rowp[idx + 2] = bfpack(l0, l1);
            }
        }
    }
}

// ------------------------- fused 8-layer kernel --------------------------
// grid (HT, KK): block = one 64-sample tile of expert k's bucket.
__global__ __launch_bounds__(256) void k_fused(
    const float* __restrict__ z,
    const float* __restrict__ bb0, const float* __restrict__ bb1,
    const float* __restrict__ bb2, const float* __restrict__ bb3,
    const float* __restrict__ hb0, const float* __restrict__ hb1,
    const float* __restrict__ hb2, const float* __restrict__ hb3,
    float* __restrict__ out)
{
    __shared__ uint4 sa[TM * RSU];
    const int k      = blockIdx.y;
    const int cstart = g_offsets[k];
    const int cend   = g_offsets[k + 1];
    const int base   = cstart + blockIdx.x * TM;
    if (base >= cend) return;
    const int tid = threadIdx.x;

    // stage z: gather + split + permute (kgroup 0 only, In=16)
    {
        int e = tid;               // TM*4 = 256 slots, one per thread
        int r = e >> 2, t = e & 3;
        float v0 = 0.f, v1 = 0.f, v2 = 0.f, v3 = 0.f;
        if (base + r < cend) {
            const float* zp = z + (size_t)g_sorted[base + r] * ZZ + 2 * t;
            v0 = zp[0]; v1 = zp[1]; v2 = zp[8]; v3 = zp[9];
        }
        float h0,l0,h1,l1,h2,l2,h3,l3;
        bsplit(v0,h0,l0); bsplit(v1,h1,l1); bsplit(v2,h2,l2); bsplit(v3,h3,l3);
        uint4 u;
        u.x = bfpack(h0,h1); u.y = bfpack(h2,h3);
        u.z = bfpack(l0,l1); u.w = bfpack(l2,l3);
        sa[r * RSU + t] = u;
    }
    __syncthreads();

    const int wid = tid >> 5, lane = tid & 31;
    const int g = lane >> 2, t = lane & 3;
    const int m0 = (wid & 1) * 32;
    const int n0 = (wid >> 1) * 32;
    float C[2][4][4];

    // backbone layer 0 (In=16)
    init_bias<4>(C, bb0, n0, t);
    gemm_warp<1, 4>(sa, g_wsplit + OFF_BW0, m0, n0, g, t, C);
    __syncthreads(); epi_relu_split<4>(sa, C, m0, n0, g, t); __syncthreads();

    // backbone layers 1..3
    init_bias<4>(C, bb1, n0, t);
    gemm_warp<8, 4>(sa, g_wsplit + OFF_BW1, m0, n0, g, t, C);
    __syncthreads(); epi_relu_split<4>(sa, C, m0, n0, g, t); __syncthreads();

    init_bias<4>(C, bb2, n0, t);
    gemm_warp<8, 4>(sa, g_wsplit + OFF_BW2, m0, n0, g, t, C);
    __syncthreads(); epi_relu_split<4>(sa, C, m0, n0, g, t); __syncthreads();

    init_bias<4>(C, bb3, n0, t);
    gemm_warp<8, 4>(sa, g_wsplit + OFF_BW3, m0, n0, g, t, C);
    __syncthreads(); epi_relu_split<4>(sa, C, m0, n0, g, t); __syncthreads();

    // head layers 0..2 (expert k)
    init_bias<4>(C, hb0 + k * HH, n0, t);
    gemm_warp<8, 4>(sa, g_wsplit + OFF_HW0 + (size_t)k * 4096, m0, n0, g, t, C);
    __syncthreads(); epi_relu_split<4>(sa, C, m0, n0, g, t); __syncthreads();

    init_bias<4>(C, hb1 + k * HH, n0, t);
    gemm_warp<8, 4>(sa, g_wsplit + OFF_HW1 + (size_t)k * 4096, m0, n0, g, t, C);
    __syncthreads(); epi_relu_split<4>(sa, C, m0, n0, g, t); __syncthreads();

    init_bias<4>(C, hb2 + k * HH, n0, t);
    gemm_warp<8, 4>(sa, g_wsplit + OFF_HW2 + (size_t)k * 4096, m0, n0, g, t, C);
    __syncthreads(); epi_relu_split<4>(sa, C, m0, n0, g, t); __syncthreads();

    // head layer 3: H -> D(64), no ReLU, scatter to output
    {
        const int n3 = (wid >> 1) * 16;
        init_bias<2>(C, hb3 + k * DD, n3, t);
        gemm_warp<8, 2>(sa, g_wsplit + OFF_HW3 + (size_t)k * 2048, m0, n3, g, t, C);
#pragma unroll
        for (int mf = 0; mf < 2; mf++) {
#pragma unroll
            for (int half = 0; half < 2; half++) {
                int p = base + m0 + mf * 16 + half * 8 + g;
                if (p < cend) {
                    int s = g_sorted[p];
#pragma unroll
                    for (int nt = 0; nt < 2; nt++) {
                        int c = n3 + nt * 8 + 2 * t;
                        *reinterpret_cast<float2*>(&out[(size_t)s * DD + c]) =
                            make_float2(C[mf][nt][half * 2], C[mf][nt][half * 2 + 1]);
                    }
                }
            }
        }
    }
}

// ----------------------------- launcher ----------------------------------
extern "C" void kernel_launch(void* const* d_in, const int* in_sizes, int n_in,
                              void* d_out, int out_size)
{
    const float* z   = (const float*)d_in[0];
    const int*   y   = (const int*)  d_in[1];
    const float* bw0 = (const float*)d_in[2];
    const float* bb0 = (const float*)d_in[3];
    const float* bw1 = (const float*)d_in[4];
    const float* bb1 = (const float*)d_in[5];
    const float* bw2 = (const float*)d_in[6];
    const float* bb2 = (const float*)d_in[7];
    const float* bw3 = (const float*)d_in[8];
    const float* bb3 = (const float*)d_in[9];
    const float* hw0 = (const float*)d_in[10];
    const float* hb0 = (const float*)d_in[11];
    const float* hw1 = (const float*)d_in[12];
    const float* hb1 = (const float*)d_in[13];
    const float* hw2 = (const float*)d_in[14];
    const float* hb2 = (const float*)d_in[15];
    const float* hw3 = (const float*)d_in[16];
    const float* hb3 = (const float*)d_in[17];
    float* out = (float*)d_out;

    k_init<<<1, 32>>>();
    k_hist<<<NBLK, TPB_H>>>(y);
    k_scan<<<1, 1>>>();
    k_scatter<<<NBLK, TPB_H>>>(y);
    k_wsplit<<<(242176 + 255) / 256, 256>>>(bw0, bw1, bw2, bw3, hw0, hw1, hw2, hw3);
    dim3 fgrid(HT, KK);
    k_fused<<<fgrid, 256>>>(z, bb0, bb1, bb2, bb3, hb0, hb1, hb2, hb3, out);
}